// round 1
// baseline (speedup 1.0000x reference)
#include <cuda_runtime.h>
#include <math.h>

#define DD   128
#define MAXN 50000

// Scratch (allocation-free rule: __device__ globals)
__device__ float g_dinv[MAXN];
__device__ float g_buf1[(size_t)MAXN * DD];
__device__ float g_buf2[(size_t)MAXN * DD];

// ---------------------------------------------------------------------------
// Degree / normalization
// ---------------------------------------------------------------------------
__global__ void k_init_deg(float* __restrict__ deg, int n) {
    int i = blockIdx.x * blockDim.x + threadIdx.x;
    if (i < n) deg[i] = 1.0f;  // self-loop
}

__global__ void k_count(const int* __restrict__ dst, float* __restrict__ deg, int E) {
    int i = blockIdx.x * blockDim.x + threadIdx.x;
    if (i < E) atomicAdd(&deg[dst[i]], 1.0f);
}

__global__ void k_rsqrt(float* __restrict__ deg, int n) {
    int i = blockIdx.x * blockDim.x + threadIdx.x;
    if (i < n) deg[i] = rsqrtf(deg[i]);
}

// ---------------------------------------------------------------------------
// GEMM: C[n,128] = A[n,128] @ W[128,128]
// 64-row tiles, BK=32, 256 threads, each thread computes 4 rows x 8 cols.
// ---------------------------------------------------------------------------
__global__ __launch_bounds__(256) void k_gemm(const float* __restrict__ A,
                                              const float* __restrict__ W,
                                              float* __restrict__ C, int n) {
    __shared__ float As[64][33];   // +1 pad to dodge bank conflicts
    __shared__ float Ws[32][128];

    int tid  = threadIdx.x;
    int tx   = tid & 15;   // col group (8 cols each)
    int ty   = tid >> 4;   // row group (4 rows each)
    int row0 = blockIdx.x * 64;

    float acc[4][8];
#pragma unroll
    for (int i = 0; i < 4; i++)
#pragma unroll
        for (int j = 0; j < 8; j++) acc[i][j] = 0.0f;

    for (int k0 = 0; k0 < DD; k0 += 32) {
        // A tile: 64 x 32 = 512 float4, 2 per thread
#pragma unroll
        for (int t = 0; t < 2; t++) {
            int idx = tid + t * 256;          // 0..511
            int r   = idx >> 3;               // 8 float4 per row
            int c   = (idx & 7) << 2;
            float4 v = make_float4(0.f, 0.f, 0.f, 0.f);
            int gr = row0 + r;
            if (gr < n) v = *(const float4*)(A + (size_t)gr * DD + k0 + c);
            As[r][c]     = v.x;
            As[r][c + 1] = v.y;
            As[r][c + 2] = v.z;
            As[r][c + 3] = v.w;
        }
        // W tile: 32 x 128 = 1024 float4, 4 per thread
#pragma unroll
        for (int t = 0; t < 4; t++) {
            int idx = tid + t * 256;          // 0..1023
            int r   = idx >> 5;               // 32 float4 per row
            int c   = (idx & 31) << 2;
            *(float4*)&Ws[r][c] = *(const float4*)(W + (size_t)(k0 + r) * DD + c);
        }
        __syncthreads();

#pragma unroll
        for (int k = 0; k < 32; k++) {
            float a[4];
#pragma unroll
            for (int i = 0; i < 4; i++) a[i] = As[ty * 4 + i][k];
            float4 w0 = *(float4*)&Ws[k][tx * 8];
            float4 w1 = *(float4*)&Ws[k][tx * 8 + 4];
#pragma unroll
            for (int i = 0; i < 4; i++) {
                acc[i][0] += a[i] * w0.x;
                acc[i][1] += a[i] * w0.y;
                acc[i][2] += a[i] * w0.z;
                acc[i][3] += a[i] * w0.w;
                acc[i][4] += a[i] * w1.x;
                acc[i][5] += a[i] * w1.y;
                acc[i][6] += a[i] * w1.z;
                acc[i][7] += a[i] * w1.w;
            }
        }
        __syncthreads();
    }

#pragma unroll
    for (int i = 0; i < 4; i++) {
        int gr = row0 + ty * 4 + i;
        if (gr < n) {
            float4 o0 = make_float4(acc[i][0], acc[i][1], acc[i][2], acc[i][3]);
            float4 o1 = make_float4(acc[i][4], acc[i][5], acc[i][6], acc[i][7]);
            *(float4*)(C + (size_t)gr * DD + tx * 8)     = o0;
            *(float4*)(C + (size_t)gr * DD + tx * 8 + 4) = o1;
        }
    }
}

// ---------------------------------------------------------------------------
// Self-loop initialization: agg[v,:] = dinv[v]^2 * h[v,:]
// One thread per float4 (n*32 threads).
// ---------------------------------------------------------------------------
__global__ void k_selfloop(const float* __restrict__ h, const float* __restrict__ dinv,
                           float* __restrict__ agg, int n) {
    int i = blockIdx.x * blockDim.x + threadIdx.x;
    if (i >= n * 32) return;
    int v   = i >> 5;
    float w = dinv[v];
    w       = w * w;
    float4 t = ((const float4*)h)[i];
    t.x *= w; t.y *= w; t.z *= w; t.w *= w;
    ((float4*)agg)[i] = t;
}

// ---------------------------------------------------------------------------
// Edge scatter: agg[dst,:] += dinv[src]*dinv[dst] * h[src,:]
// One warp per edge; lane l handles float4 chunk l (32 x 16B = 512B row).
// Vector reduction via red.global.add.v4.f32 (sm_90+, no return trip).
// ---------------------------------------------------------------------------
__device__ __forceinline__ void red_add_f32x4(float4* addr, float4 v) {
    asm volatile("red.global.add.v4.f32 [%0], {%1, %2, %3, %4};"
                 :: "l"(addr), "f"(v.x), "f"(v.y), "f"(v.z), "f"(v.w)
                 : "memory");
}

__global__ __launch_bounds__(256) void k_scatter(const float* __restrict__ h,
                                                 const int* __restrict__ src,
                                                 const int* __restrict__ dst,
                                                 const float* __restrict__ dinv,
                                                 float* __restrict__ agg, int E) {
    int gw   = (blockIdx.x * (blockDim.x >> 5)) + (threadIdx.x >> 5);
    int lane = threadIdx.x & 31;
    if (gw >= E) return;
    int s = src[gw];
    int d = dst[gw];
    float w = dinv[s] * dinv[d];
    float4 v = ((const float4*)(h + (size_t)s * DD))[lane];
    v.x *= w; v.y *= w; v.z *= w; v.w *= w;
    red_add_f32x4(((float4*)(agg + (size_t)d * DD)) + lane, v);
}

// ---------------------------------------------------------------------------
// Epilogue: in-place x = elu(x + b)
// ---------------------------------------------------------------------------
__device__ __forceinline__ float eluf(float x) {
    return x > 0.0f ? x : expm1f(x);
}

__global__ void k_bias_elu(float* __restrict__ agg, const float* __restrict__ b, int n) {
    int i = blockIdx.x * blockDim.x + threadIdx.x;
    if (i >= n * 32) return;
    int c4    = i & 31;
    float4 bb = ((const float4*)b)[c4];
    float4 t  = ((float4*)agg)[i];
    t.x = eluf(t.x + bb.x);
    t.y = eluf(t.y + bb.y);
    t.z = eluf(t.z + bb.z);
    t.w = eluf(t.w + bb.w);
    ((float4*)agg)[i] = t;
}

// ---------------------------------------------------------------------------
// Launch
// ---------------------------------------------------------------------------
extern "C" void kernel_launch(void* const* d_in, const int* in_sizes, int n_in,
                              void* d_out, int out_size) {
    const float* x  = (const float*)d_in[0];
    const int*   ei = (const int*)d_in[1];
    const float* W1 = (const float*)d_in[2];
    const float* b1 = (const float*)d_in[3];
    const float* W2 = (const float*)d_in[4];
    const float* b2 = (const float*)d_in[5];
    float* out = (float*)d_out;

    int N = in_sizes[0] / DD;
    int E = in_sizes[1] / 2;
    const int* src = ei;       // edge_index[0]
    const int* dst = ei + E;   // edge_index[1]

    float *dinv, *buf1, *buf2;
    cudaGetSymbolAddress((void**)&dinv, g_dinv);
    cudaGetSymbolAddress((void**)&buf1, g_buf1);
    cudaGetSymbolAddress((void**)&buf2, g_buf2);

    const int T = 256;
    int nv = N * 32;  // float4 count per feature buffer

    // Normalization coefficients
    k_init_deg<<<(N + T - 1) / T, T>>>(dinv, N);
    k_count<<<(E + T - 1) / T, T>>>(dst, dinv, E);
    k_rsqrt<<<(N + T - 1) / T, T>>>(dinv, N);

    int gemm_grid    = (N + 63) / 64;
    int scatter_grid = (E + 7) / 8;   // 8 warps per block, 1 edge per warp

    // Layer 1: h = x@W1 ; agg = D^-1/2 A D^-1/2 h ; x1 = elu(agg + b1)
    k_gemm<<<gemm_grid, 256>>>(x, W1, buf1, N);
    k_selfloop<<<(nv + T - 1) / T, T>>>(buf1, dinv, buf2, N);
    k_scatter<<<scatter_grid, 256>>>(buf1, src, dst, dinv, buf2, E);
    k_bias_elu<<<(nv + T - 1) / T, T>>>(buf2, b1, N);

    // Layer 2: h = x1@W2 ; out = elu(agg + b2)
    k_gemm<<<gemm_grid, 256>>>(buf2, W2, buf1, N);
    k_selfloop<<<(nv + T - 1) / T, T>>>(buf1, dinv, out, N);
    k_scatter<<<scatter_grid, 256>>>(buf1, src, dst, dinv, out, E);
    k_bias_elu<<<(nv + T - 1) / T, T>>>(out, b2, N);
}

// round 2
// speedup vs baseline: 1.3365x; 1.3365x over previous
#include <cuda_runtime.h>
#include <math.h>

#define DD   128
#define MAXN 50000
#define MAXE 800000

// Scratch (allocation-free rule: __device__ globals)
__device__ float g_dinv[MAXN];
__device__ float g_buf1[(size_t)MAXN * DD];
__device__ float g_buf2[(size_t)MAXN * DD];
__device__ int   g_cnt[MAXN];
__device__ int   g_rowptr[MAXN + 1];
__device__ int   g_cur[MAXN];
__device__ int   g_col[MAXE];

// ---------------------------------------------------------------------------
// CSR build: histogram -> scan -> fill
// ---------------------------------------------------------------------------
__global__ void k_hist(const int* __restrict__ dst, int* __restrict__ cnt, int E) {
    int i = blockIdx.x * blockDim.x + threadIdx.x;
    if (i < E) atomicAdd(&cnt[dst[i]], 1);
}

// Single-block exclusive scan over n counts -> rowptr (and cur copy).
__global__ void k_scan(const int* __restrict__ cnt, int* __restrict__ rowptr,
                       int* __restrict__ cur, int n) {
    __shared__ int sh[1024];
    __shared__ int carry;
    int tid = threadIdx.x;
    if (tid == 0) carry = 0;
    __syncthreads();
    for (int base = 0; base < n; base += 1024) {
        int v = (base + tid < n) ? cnt[base + tid] : 0;
        sh[tid] = v;
        __syncthreads();
        for (int off = 1; off < 1024; off <<= 1) {
            int t = (tid >= off) ? sh[tid - off] : 0;
            __syncthreads();
            sh[tid] += t;
            __syncthreads();
        }
        int incl = sh[tid];
        int c    = carry;
        if (base + tid < n) {
            int ex = c + incl - v;
            rowptr[base + tid] = ex;
            cur[base + tid]    = ex;
        }
        __syncthreads();
        if (tid == 1023) carry = c + incl;
        __syncthreads();
    }
    if (tid == 0) rowptr[n] = carry;
}

__global__ void k_dinv(const int* __restrict__ cnt, float* __restrict__ dinv, int n) {
    int i = blockIdx.x * blockDim.x + threadIdx.x;
    if (i < n) dinv[i] = rsqrtf((float)(cnt[i] + 1));   // +1 self-loop
}

__global__ void k_fill(const int* __restrict__ src, const int* __restrict__ dst,
                       int* __restrict__ cur, int* __restrict__ col, int E) {
    int i = blockIdx.x * blockDim.x + threadIdx.x;
    if (i < E) {
        int p  = atomicAdd(&cur[dst[i]], 1);
        col[p] = src[i];
    }
}

// ---------------------------------------------------------------------------
// GEMM with dinv epilogue: C[r,:] = dinv[r] * (A[r,:] @ W)
// 128x128 block tile, BK=16, 256 threads, 8x8 microtile.
// ---------------------------------------------------------------------------
__global__ __launch_bounds__(256) void k_gemm_scaled(const float* __restrict__ A,
                                                     const float* __restrict__ W,
                                                     const float* __restrict__ dinv,
                                                     float* __restrict__ C, int n) {
    __shared__ float As[16][132];   // [k][row], padded, 16B-aligned rows
    __shared__ float Ws[16][128];   // [k][col]

    int tid  = threadIdx.x;
    int tx   = tid & 15;            // col group (8 cols)
    int ty   = tid >> 4;            // row group (8 rows)
    int row0 = blockIdx.x * 128;

    float acc[8][8];
#pragma unroll
    for (int i = 0; i < 8; i++)
#pragma unroll
        for (int j = 0; j < 8; j++) acc[i][j] = 0.0f;

    for (int k0 = 0; k0 < DD; k0 += 16) {
        // A tile: 128 rows x 16 k = 512 float4, 2 per thread, store transposed
#pragma unroll
        for (int t = 0; t < 2; t++) {
            int idx = tid + t * 256;          // 0..511
            int r   = idx >> 2;               // 4 float4 per row
            int c   = (idx & 3) << 2;
            float4 v = make_float4(0.f, 0.f, 0.f, 0.f);
            int gr = row0 + r;
            if (gr < n) v = *(const float4*)(A + (size_t)gr * DD + k0 + c);
            As[c][r]     = v.x;
            As[c + 1][r] = v.y;
            As[c + 2][r] = v.z;
            As[c + 3][r] = v.w;
        }
        // W tile: 16 k x 128 cols = 512 float4, 2 per thread
#pragma unroll
        for (int t = 0; t < 2; t++) {
            int idx = tid + t * 256;          // 0..511
            int r   = idx >> 5;               // 32 float4 per row
            int c   = (idx & 31) << 2;
            *(float4*)&Ws[r][c] = *(const float4*)(W + (size_t)(k0 + r) * DD + c);
        }
        __syncthreads();

#pragma unroll
        for (int k = 0; k < 16; k++) {
            float4 a0 = *(float4*)&As[k][ty * 8];
            float4 a1 = *(float4*)&As[k][ty * 8 + 4];
            float4 w0 = *(float4*)&Ws[k][tx * 8];
            float4 w1 = *(float4*)&Ws[k][tx * 8 + 4];
            float av[8] = {a0.x, a0.y, a0.z, a0.w, a1.x, a1.y, a1.z, a1.w};
            float wv[8] = {w0.x, w0.y, w0.z, w0.w, w1.x, w1.y, w1.z, w1.w};
#pragma unroll
            for (int i = 0; i < 8; i++)
#pragma unroll
                for (int j = 0; j < 8; j++) acc[i][j] += av[i] * wv[j];
        }
        __syncthreads();
    }

#pragma unroll
    for (int i = 0; i < 8; i++) {
        int gr = row0 + ty * 8 + i;
        if (gr < n) {
            float s = dinv[gr];
            float4 o0 = make_float4(acc[i][0] * s, acc[i][1] * s, acc[i][2] * s, acc[i][3] * s);
            float4 o1 = make_float4(acc[i][4] * s, acc[i][5] * s, acc[i][6] * s, acc[i][7] * s);
            *(float4*)(C + (size_t)gr * DD + tx * 8)     = o0;
            *(float4*)(C + (size_t)gr * DD + tx * 8 + 4) = o1;
        }
    }
}

// ---------------------------------------------------------------------------
// Fused CSR gather + self-loop + bias + ELU.
// One warp per dst node; lane l owns float4 chunk l.
//   out[d,:] = elu( dinv[d] * (h'[d,:] + sum_{s in N(d)} h'[s,:]) + b )
// where h' = dinv .* (x @ W) from the GEMM epilogue.
// ---------------------------------------------------------------------------
__device__ __forceinline__ float eluf(float x) { return x > 0.0f ? x : expm1f(x); }

__global__ __launch_bounds__(256) void k_gather(const float* __restrict__ hp,
                                                const int* __restrict__ rowptr,
                                                const int* __restrict__ colv,
                                                const float* __restrict__ dinv,
                                                const float* __restrict__ b,
                                                float* __restrict__ outp, int n) {
    int d    = blockIdx.x * 8 + (threadIdx.x >> 5);
    int lane = threadIdx.x & 31;
    if (d >= n) return;

    const float4* hp4 = (const float4*)hp;

    int start = rowptr[d];
    int end   = rowptr[d + 1];

    // self-loop contribution
    float4 acc = hp4[(size_t)d * 32 + lane];

    for (int base = start; base < end; base += 32) {
        int cnt  = min(32, end - base);
        int sidx = (base + lane < end) ? colv[base + lane] : 0;
        int j = 0;
        for (; j + 4 <= cnt; j += 4) {
            int s0 = __shfl_sync(0xffffffffu, sidx, j);
            int s1 = __shfl_sync(0xffffffffu, sidx, j + 1);
            int s2 = __shfl_sync(0xffffffffu, sidx, j + 2);
            int s3 = __shfl_sync(0xffffffffu, sidx, j + 3);
            float4 v0 = hp4[(size_t)s0 * 32 + lane];
            float4 v1 = hp4[(size_t)s1 * 32 + lane];
            float4 v2 = hp4[(size_t)s2 * 32 + lane];
            float4 v3 = hp4[(size_t)s3 * 32 + lane];
            acc.x += v0.x + v1.x + v2.x + v3.x;
            acc.y += v0.y + v1.y + v2.y + v3.y;
            acc.z += v0.z + v1.z + v2.z + v3.z;
            acc.w += v0.w + v1.w + v2.w + v3.w;
        }
        for (; j < cnt; j++) {
            int s    = __shfl_sync(0xffffffffu, sidx, j);
            float4 v = hp4[(size_t)s * 32 + lane];
            acc.x += v.x; acc.y += v.y; acc.z += v.z; acc.w += v.w;
        }
    }

    float w    = dinv[d];
    float4 bb  = ((const float4*)b)[lane];
    acc.x = eluf(acc.x * w + bb.x);
    acc.y = eluf(acc.y * w + bb.y);
    acc.z = eluf(acc.z * w + bb.z);
    acc.w = eluf(acc.w * w + bb.w);
    ((float4*)outp)[(size_t)d * 32 + lane] = acc;
}

// ---------------------------------------------------------------------------
// Launch
// ---------------------------------------------------------------------------
extern "C" void kernel_launch(void* const* d_in, const int* in_sizes, int n_in,
                              void* d_out, int out_size) {
    const float* x  = (const float*)d_in[0];
    const int*   ei = (const int*)d_in[1];
    const float* W1 = (const float*)d_in[2];
    const float* b1 = (const float*)d_in[3];
    const float* W2 = (const float*)d_in[4];
    const float* b2 = (const float*)d_in[5];
    float* out = (float*)d_out;

    int N = in_sizes[0] / DD;
    int E = in_sizes[1] / 2;
    const int* src = ei;       // edge_index[0]
    const int* dst = ei + E;   // edge_index[1]

    float *dinv, *buf1, *buf2;
    int *cnt, *rowptr, *cur, *col;
    cudaGetSymbolAddress((void**)&dinv, g_dinv);
    cudaGetSymbolAddress((void**)&buf1, g_buf1);
    cudaGetSymbolAddress((void**)&buf2, g_buf2);
    cudaGetSymbolAddress((void**)&cnt, g_cnt);
    cudaGetSymbolAddress((void**)&rowptr, g_rowptr);
    cudaGetSymbolAddress((void**)&cur, g_cur);
    cudaGetSymbolAddress((void**)&col, g_col);

    const int T = 256;

    // CSR build + normalization
    cudaMemsetAsync(cnt, 0, (size_t)N * sizeof(int));
    k_hist<<<(E + T - 1) / T, T>>>(dst, cnt, E);
    k_scan<<<1, 1024>>>(cnt, rowptr, cur, N);
    k_dinv<<<(N + T - 1) / T, T>>>(cnt, dinv, N);
    k_fill<<<(E + T - 1) / T, T>>>(src, dst, cur, col, E);

    int gemm_grid   = (N + 127) / 128;
    int gather_grid = (N + 7) / 8;   // 8 warps/block, 1 node per warp

    // Layer 1
    k_gemm_scaled<<<gemm_grid, 256>>>(x, W1, dinv, buf1, N);
    k_gather<<<gather_grid, 256>>>(buf1, rowptr, col, dinv, b1, buf2, N);

    // Layer 2
    k_gemm_scaled<<<gemm_grid, 256>>>(buf2, W2, dinv, buf1, N);
    k_gather<<<gather_grid, 256>>>(buf1, rowptr, col, dinv, b2, out, N);
}

// round 3
// speedup vs baseline: 1.7581x; 1.3154x over previous
#include <cuda_runtime.h>
#include <math.h>

#define DD   128
#define MAXN 50000
#define MAXE 800000

// Scratch (allocation-free rule: __device__ globals)
__device__ __align__(16) float g_dinv[MAXN];
__device__ __align__(16) float g_buf1[(size_t)MAXN * DD];
__device__ __align__(16) float g_buf2[(size_t)MAXN * DD];
__device__ __align__(16) int   g_cnt[MAXN];
__device__ __align__(16) int   g_rowptr[MAXN + 4];
__device__ __align__(16) int   g_cur[MAXN];
__device__ __align__(16) int   g_col[MAXE];
__device__ __align__(16) int   g_part[256];

// ---------------------------------------------------------------------------
// Histogram of dst (4 edges per thread, vectorized load)
// ---------------------------------------------------------------------------
__global__ void k_hist(const int* __restrict__ dst, int* __restrict__ cnt, int E) {
    int i = (blockIdx.x * blockDim.x + threadIdx.x) * 4;
    if (i + 3 < E && ((((size_t)dst) & 15) == 0)) {
        int4 d = *(const int4*)(dst + i);
        atomicAdd(&cnt[d.x], 1);
        atomicAdd(&cnt[d.y], 1);
        atomicAdd(&cnt[d.z], 1);
        atomicAdd(&cnt[d.w], 1);
    } else {
        for (int j = 0; j < 4; j++)
            if (i + j < E) atomicAdd(&cnt[dst[i + j]], 1);
    }
}

// ---------------------------------------------------------------------------
// 3-phase exclusive scan of cnt[0..n) -> rowptr / cur, plus dinv epilogue.
// Phase 1: per-block (1024 elems) sums.
// ---------------------------------------------------------------------------
__global__ __launch_bounds__(256) void k_scan_partial(const int* __restrict__ cnt,
                                                      int* __restrict__ part, int n) {
    __shared__ int sh[8];
    int tid  = threadIdx.x;
    int base = blockIdx.x * 1024 + tid * 4;
    int s = 0;
    if (base + 3 < n) {
        int4 v = *(const int4*)(cnt + base);
        s = v.x + v.y + v.z + v.w;
    } else {
        for (int j = 0; j < 4; j++)
            if (base + j < n) s += cnt[base + j];
    }
#pragma unroll
    for (int o = 16; o; o >>= 1) s += __shfl_down_sync(0xffffffffu, s, o);
    if ((tid & 31) == 0) sh[tid >> 5] = s;
    __syncthreads();
    if (tid < 8) {
        s = sh[tid];
#pragma unroll
        for (int o = 4; o; o >>= 1) s += __shfl_down_sync(0x000000ffu, s, o);
        if (tid == 0) part[blockIdx.x] = s;
    }
}

// Phase 2: scan the (<=256) block partials in one small block; also write total.
__global__ void k_scan_tops(int* __restrict__ part, int* __restrict__ total, int nb) {
    __shared__ int sh[256];
    int t = threadIdx.x;
    int v = (t < nb) ? part[t] : 0;
    sh[t] = v;
    __syncthreads();
    for (int o = 1; o < 256; o <<= 1) {
        int u = (t >= o) ? sh[t - o] : 0;
        __syncthreads();
        sh[t] += u;
        __syncthreads();
    }
    if (t < nb) part[t] = sh[t] - v;      // exclusive
    if (t == 255) *total = sh[255];
}

// Phase 3: downsweep — exclusive scan per element, write rowptr/cur/dinv.
__global__ __launch_bounds__(256) void k_scan_down(const int* __restrict__ cnt,
                                                   const int* __restrict__ part,
                                                   int* __restrict__ rowptr,
                                                   int* __restrict__ cur,
                                                   float* __restrict__ dinv, int n) {
    __shared__ int wsum[8];
    int tid  = threadIdx.x;
    int lane = tid & 31, wid = tid >> 5;
    int base = blockIdx.x * 1024 + tid * 4;

    int4 c = make_int4(0, 0, 0, 0);
    if (base + 3 < n) c = *(const int4*)(cnt + base);
    else {
        int* cp = (int*)&c;
        for (int j = 0; j < 4; j++) cp[j] = (base + j < n) ? cnt[base + j] : 0;
    }
    int s0 = c.x, s1 = s0 + c.y, s2 = s1 + c.z, s3 = s2 + c.w;
    int ts = s3, sc = ts;
#pragma unroll
    for (int o = 1; o < 32; o <<= 1) {
        int u = __shfl_up_sync(0xffffffffu, sc, o);
        if (lane >= o) sc += u;
    }
    if (lane == 31) wsum[wid] = sc;
    __syncthreads();
    if (wid == 0) {
        int w = (lane < 8) ? wsum[lane] : 0;
#pragma unroll
        for (int o = 1; o < 8; o <<= 1) {
            int u = __shfl_up_sync(0xffffffffu, w, o);
            if (lane >= o) w += u;
        }
        if (lane < 8) wsum[lane] = w;
    }
    __syncthreads();

    int off = part[blockIdx.x] + (wid ? wsum[wid - 1] : 0) + (sc - ts);
    if (base + 3 < n) {
        int4 r = make_int4(off, off + s0, off + s1, off + s2);
        *(int4*)(rowptr + base) = r;
        *(int4*)(cur + base)    = r;
        float4 dv = make_float4(rsqrtf((float)(c.x + 1)), rsqrtf((float)(c.y + 1)),
                                rsqrtf((float)(c.z + 1)), rsqrtf((float)(c.w + 1)));
        *(float4*)(dinv + base) = dv;
    } else {
        int rr[4] = {off, off + s0, off + s1, off + s2};
        int* cp = (int*)&c;
        for (int j = 0; j < 4; j++)
            if (base + j < n) {
                rowptr[base + j] = rr[j];
                cur[base + j]    = rr[j];
                dinv[base + j]   = rsqrtf((float)(cp[j] + 1));
            }
    }
}

// ---------------------------------------------------------------------------
// CSR fill (4 edges per thread)
// ---------------------------------------------------------------------------
__global__ void k_fill(const int* __restrict__ src, const int* __restrict__ dst,
                       int* __restrict__ cur, int* __restrict__ col, int E) {
    int i = (blockIdx.x * blockDim.x + threadIdx.x) * 4;
    if (i + 3 < E && ((((size_t)src) & 15) == 0) && ((((size_t)dst) & 15) == 0)) {
        int4 s = *(const int4*)(src + i);
        int4 d = *(const int4*)(dst + i);
        col[atomicAdd(&cur[d.x], 1)] = s.x;
        col[atomicAdd(&cur[d.y], 1)] = s.y;
        col[atomicAdd(&cur[d.z], 1)] = s.z;
        col[atomicAdd(&cur[d.w], 1)] = s.w;
    } else {
        for (int j = 0; j < 4; j++)
            if (i + j < E) col[atomicAdd(&cur[dst[i + j]], 1)] = src[i + j];
    }
}

// ---------------------------------------------------------------------------
// GEMM with dinv epilogue: C[r,:] = dinv[r] * (A[r,:] @ W)
// 128x128 block tile, BK=16, 256 threads, 8x8 microtile.
// ---------------------------------------------------------------------------
__global__ __launch_bounds__(256) void k_gemm_scaled(const float* __restrict__ A,
                                                     const float* __restrict__ W,
                                                     const float* __restrict__ dinv,
                                                     float* __restrict__ C, int n) {
    __shared__ float As[16][132];
    __shared__ float Ws[16][128];

    int tid  = threadIdx.x;
    int tx   = tid & 15;
    int ty   = tid >> 4;
    int row0 = blockIdx.x * 128;

    float acc[8][8];
#pragma unroll
    for (int i = 0; i < 8; i++)
#pragma unroll
        for (int j = 0; j < 8; j++) acc[i][j] = 0.0f;

    for (int k0 = 0; k0 < DD; k0 += 16) {
#pragma unroll
        for (int t = 0; t < 2; t++) {
            int idx = tid + t * 256;
            int r   = idx >> 2;
            int c   = (idx & 3) << 2;
            float4 v = make_float4(0.f, 0.f, 0.f, 0.f);
            int gr = row0 + r;
            if (gr < n) v = *(const float4*)(A + (size_t)gr * DD + k0 + c);
            As[c][r]     = v.x;
            As[c + 1][r] = v.y;
            As[c + 2][r] = v.z;
            As[c + 3][r] = v.w;
        }
#pragma unroll
        for (int t = 0; t < 2; t++) {
            int idx = tid + t * 256;
            int r   = idx >> 5;
            int c   = (idx & 31) << 2;
            *(float4*)&Ws[r][c] = *(const float4*)(W + (size_t)(k0 + r) * DD + c);
        }
        __syncthreads();

#pragma unroll
        for (int k = 0; k < 16; k++) {
            float4 a0 = *(float4*)&As[k][ty * 8];
            float4 a1 = *(float4*)&As[k][ty * 8 + 4];
            float4 w0 = *(float4*)&Ws[k][tx * 8];
            float4 w1 = *(float4*)&Ws[k][tx * 8 + 4];
            float av[8] = {a0.x, a0.y, a0.z, a0.w, a1.x, a1.y, a1.z, a1.w};
            float wv[8] = {w0.x, w0.y, w0.z, w0.w, w1.x, w1.y, w1.z, w1.w};
#pragma unroll
            for (int i = 0; i < 8; i++)
#pragma unroll
                for (int j = 0; j < 8; j++) acc[i][j] += av[i] * wv[j];
        }
        __syncthreads();
    }

#pragma unroll
    for (int i = 0; i < 8; i++) {
        int gr = row0 + ty * 8 + i;
        if (gr < n) {
            float s = dinv[gr];
            float4 o0 = make_float4(acc[i][0] * s, acc[i][1] * s, acc[i][2] * s, acc[i][3] * s);
            float4 o1 = make_float4(acc[i][4] * s, acc[i][5] * s, acc[i][6] * s, acc[i][7] * s);
            *(float4*)(C + (size_t)gr * DD + tx * 8)     = o0;
            *(float4*)(C + (size_t)gr * DD + tx * 8 + 4) = o1;
        }
    }
}

// ---------------------------------------------------------------------------
// Fused CSR gather + self-loop + bias + ELU. One warp per dst node.
// ---------------------------------------------------------------------------
__device__ __forceinline__ float eluf(float x) { return x > 0.0f ? x : expm1f(x); }

__global__ __launch_bounds__(256) void k_gather(const float* __restrict__ hp,
                                                const int* __restrict__ rowptr,
                                                const int* __restrict__ colv,
                                                const float* __restrict__ dinv,
                                                const float* __restrict__ b,
                                                float* __restrict__ outp, int n) {
    int d    = blockIdx.x * 8 + (threadIdx.x >> 5);
    int lane = threadIdx.x & 31;
    if (d >= n) return;

    const float4* hp4 = (const float4*)hp;

    int start = rowptr[d];
    int end   = rowptr[d + 1];

    float4 acc = hp4[(size_t)d * 32 + lane];   // self-loop

    for (int base = start; base < end; base += 32) {
        int cnt  = min(32, end - base);
        int sidx = (base + lane < end) ? colv[base + lane] : 0;
        int j = 0;
        for (; j + 4 <= cnt; j += 4) {
            int s0 = __shfl_sync(0xffffffffu, sidx, j);
            int s1 = __shfl_sync(0xffffffffu, sidx, j + 1);
            int s2 = __shfl_sync(0xffffffffu, sidx, j + 2);
            int s3 = __shfl_sync(0xffffffffu, sidx, j + 3);
            float4 v0 = hp4[(size_t)s0 * 32 + lane];
            float4 v1 = hp4[(size_t)s1 * 32 + lane];
            float4 v2 = hp4[(size_t)s2 * 32 + lane];
            float4 v3 = hp4[(size_t)s3 * 32 + lane];
            acc.x += v0.x + v1.x + v2.x + v3.x;
            acc.y += v0.y + v1.y + v2.y + v3.y;
            acc.z += v0.z + v1.z + v2.z + v3.z;
            acc.w += v0.w + v1.w + v2.w + v3.w;
        }
        for (; j < cnt; j++) {
            int s    = __shfl_sync(0xffffffffu, sidx, j);
            float4 v = hp4[(size_t)s * 32 + lane];
            acc.x += v.x; acc.y += v.y; acc.z += v.z; acc.w += v.w;
        }
    }

    float w   = dinv[d];
    float4 bb = ((const float4*)b)[lane];
    acc.x = eluf(acc.x * w + bb.x);
    acc.y = eluf(acc.y * w + bb.y);
    acc.z = eluf(acc.z * w + bb.z);
    acc.w = eluf(acc.w * w + bb.w);
    ((float4*)outp)[(size_t)d * 32 + lane] = acc;
}

// ---------------------------------------------------------------------------
// Launch
// ---------------------------------------------------------------------------
extern "C" void kernel_launch(void* const* d_in, const int* in_sizes, int n_in,
                              void* d_out, int out_size) {
    const float* x  = (const float*)d_in[0];
    const int*   ei = (const int*)d_in[1];
    const float* W1 = (const float*)d_in[2];
    const float* b1 = (const float*)d_in[3];
    const float* W2 = (const float*)d_in[4];
    const float* b2 = (const float*)d_in[5];
    float* out = (float*)d_out;

    int N = in_sizes[0] / DD;
    int E = in_sizes[1] / 2;
    const int* src = ei;       // edge_index[0]
    const int* dst = ei + E;   // edge_index[1]

    float *dinv, *buf1, *buf2;
    int *cnt, *rowptr, *cur, *col, *part;
    cudaGetSymbolAddress((void**)&dinv, g_dinv);
    cudaGetSymbolAddress((void**)&buf1, g_buf1);
    cudaGetSymbolAddress((void**)&buf2, g_buf2);
    cudaGetSymbolAddress((void**)&cnt, g_cnt);
    cudaGetSymbolAddress((void**)&rowptr, g_rowptr);
    cudaGetSymbolAddress((void**)&cur, g_cur);
    cudaGetSymbolAddress((void**)&col, g_col);
    cudaGetSymbolAddress((void**)&part, g_part);

    const int T  = 256;
    int nb       = (N + 1023) / 1024;          // scan blocks (<=256 partials)
    int egrid4   = (E / 4 + T - 1) / T;        // 4 edges/thread kernels

    // CSR build + normalization
    cudaMemsetAsync(cnt, 0, (size_t)N * sizeof(int));
    k_hist<<<egrid4, T>>>(dst, cnt, E);
    k_scan_partial<<<nb, T>>>(cnt, part, N);
    k_scan_tops<<<1, 256>>>(part, rowptr + N, nb);
    k_scan_down<<<nb, T>>>(cnt, part, rowptr, cur, dinv, N);
    k_fill<<<egrid4, T>>>(src, dst, cur, col, E);

    int gemm_grid   = (N + 127) / 128;
    int gather_grid = (N + 7) / 8;

    // Layer 1
    k_gemm_scaled<<<gemm_grid, 256>>>(x, W1, dinv, buf1, N);
    k_gather<<<gather_grid, 256>>>(buf1, rowptr, col, dinv, b1, buf2, N);

    // Layer 2
    k_gemm_scaled<<<gemm_grid, 256>>>(buf2, W2, dinv, buf1, N);
    k_gather<<<gather_grid, 256>>>(buf1, rowptr, col, dinv, b2, out, N);
}

// round 5
// speedup vs baseline: 2.4087x; 1.3701x over previous
#include <cuda_runtime.h>
#include <cuda_bf16.h>
#include <math.h>
#include <stdint.h>

#define DD   128
#define MAXN 50000
#define MAXE 800000

// Scratch (allocation-free rule: __device__ globals)
__device__ __align__(16) float   g_dinv[MAXN];
__device__ __align__(16) float   g_buf1[(size_t)MAXN * DD];
__device__ __align__(16) float   g_buf2[(size_t)MAXN * DD];
__device__ __align__(16) int     g_cnt[MAXN];
__device__ __align__(16) int     g_rowptr[MAXN + 4];
__device__ __align__(16) int     g_cur[MAXN];
__device__ __align__(16) int     g_col[MAXE];
__device__ __align__(16) int     g_part[256];
// Pre-split/transposed/swizzled W image:
// [kh0: Bhi 16KB | Blo 16KB][kh1: Bhi 16KB | Blo 16KB]  (Bt[n][k] bf16, SW128)
__device__ __align__(16) uint8_t g_wb[65536];

// ---------------------------------------------------------------------------
// Helpers (sm_80+ only: ldmatrix + mma.sync — NO tcgen05, target is sm_103)
// ---------------------------------------------------------------------------
__device__ __forceinline__ uint32_t swz128(uint32_t off) {
    return off ^ ((off >> 3) & 0x70);
}
__device__ __forceinline__ uint32_t smem_u32(const void* p) {
    return (uint32_t)__cvta_generic_to_shared(p);
}

__device__ __forceinline__ void ldsm_x4(uint32_t& r0, uint32_t& r1,
                                        uint32_t& r2, uint32_t& r3, uint32_t addr) {
    asm volatile("ldmatrix.sync.aligned.m8n8.x4.shared.b16 {%0,%1,%2,%3}, [%4];"
                 : "=r"(r0), "=r"(r1), "=r"(r2), "=r"(r3) : "r"(addr));
}
__device__ __forceinline__ void ldsm_x2(uint32_t& r0, uint32_t& r1, uint32_t addr) {
    asm volatile("ldmatrix.sync.aligned.m8n8.x2.shared.b16 {%0,%1}, [%2];"
                 : "=r"(r0), "=r"(r1) : "r"(addr));
}
__device__ __forceinline__ void mma_bf16(float& d0, float& d1, float& d2, float& d3,
                                         uint32_t a0, uint32_t a1, uint32_t a2, uint32_t a3,
                                         uint32_t b0, uint32_t b1) {
    asm volatile(
        "mma.sync.aligned.m16n8k16.row.col.f32.bf16.bf16.f32 "
        "{%0,%1,%2,%3}, {%4,%5,%6,%7}, {%8,%9}, {%0,%1,%2,%3};"
        : "+f"(d0), "+f"(d1), "+f"(d2), "+f"(d3)
        : "r"(a0), "r"(a1), "r"(a2), "r"(a3), "r"(b0), "r"(b1));
}

// ---------------------------------------------------------------------------
// Histogram of dst (4 edges per thread)
// ---------------------------------------------------------------------------
__global__ void k_hist(const int* __restrict__ dst, int* __restrict__ cnt, int E) {
    int i = (blockIdx.x * blockDim.x + threadIdx.x) * 4;
    if (i + 3 < E && ((((size_t)dst) & 15) == 0)) {
        int4 d = *(const int4*)(dst + i);
        atomicAdd(&cnt[d.x], 1);
        atomicAdd(&cnt[d.y], 1);
        atomicAdd(&cnt[d.z], 1);
        atomicAdd(&cnt[d.w], 1);
    } else {
        for (int j = 0; j < 4; j++)
            if (i + j < E) atomicAdd(&cnt[dst[i + j]], 1);
    }
}

// ---------------------------------------------------------------------------
// 3-phase exclusive scan (+ dinv epilogue)
// ---------------------------------------------------------------------------
__global__ __launch_bounds__(256) void k_scan_partial(const int* __restrict__ cnt,
                                                      int* __restrict__ part, int n) {
    __shared__ int sh[8];
    int tid  = threadIdx.x;
    int base = blockIdx.x * 1024 + tid * 4;
    int s = 0;
    if (base + 3 < n) {
        int4 v = *(const int4*)(cnt + base);
        s = v.x + v.y + v.z + v.w;
    } else {
        for (int j = 0; j < 4; j++)
            if (base + j < n) s += cnt[base + j];
    }
#pragma unroll
    for (int o = 16; o; o >>= 1) s += __shfl_down_sync(0xffffffffu, s, o);
    if ((tid & 31) == 0) sh[tid >> 5] = s;
    __syncthreads();
    if (tid < 8) {
        s = sh[tid];
#pragma unroll
        for (int o = 4; o; o >>= 1) s += __shfl_down_sync(0x000000ffu, s, o);
        if (tid == 0) part[blockIdx.x] = s;
    }
}

__global__ void k_scan_tops(int* __restrict__ part, int* __restrict__ total, int nb) {
    __shared__ int sh[256];
    int t = threadIdx.x;
    int v = (t < nb) ? part[t] : 0;
    sh[t] = v;
    __syncthreads();
    for (int o = 1; o < 256; o <<= 1) {
        int u = (t >= o) ? sh[t - o] : 0;
        __syncthreads();
        sh[t] += u;
        __syncthreads();
    }
    if (t < nb) part[t] = sh[t] - v;
    if (t == 255) *total = sh[255];
}

__global__ __launch_bounds__(256) void k_scan_down(const int* __restrict__ cnt,
                                                   const int* __restrict__ part,
                                                   int* __restrict__ rowptr,
                                                   int* __restrict__ cur,
                                                   float* __restrict__ dinv, int n) {
    __shared__ int wsum[8];
    int tid  = threadIdx.x;
    int lane = tid & 31, wid = tid >> 5;
    int base = blockIdx.x * 1024 + tid * 4;

    int4 c = make_int4(0, 0, 0, 0);
    if (base + 3 < n) c = *(const int4*)(cnt + base);
    else {
        int* cp = (int*)&c;
        for (int j = 0; j < 4; j++) cp[j] = (base + j < n) ? cnt[base + j] : 0;
    }
    int s0 = c.x, s1 = s0 + c.y, s2 = s1 + c.z, s3 = s2 + c.w;
    int ts = s3, sc = ts;
#pragma unroll
    for (int o = 1; o < 32; o <<= 1) {
        int u = __shfl_up_sync(0xffffffffu, sc, o);
        if (lane >= o) sc += u;
    }
    if (lane == 31) wsum[wid] = sc;
    __syncthreads();
    if (wid == 0) {
        int w = (lane < 8) ? wsum[lane] : 0;
#pragma unroll
        for (int o = 1; o < 8; o <<= 1) {
            int u = __shfl_up_sync(0xffffffffu, w, o);
            if (lane >= o) w += u;
        }
        if (lane < 8) wsum[lane] = w;
    }
    __syncthreads();

    int off = part[blockIdx.x] + (wid ? wsum[wid - 1] : 0) + (sc - ts);
    if (base + 3 < n) {
        int4 r = make_int4(off, off + s0, off + s1, off + s2);
        *(int4*)(rowptr + base) = r;
        *(int4*)(cur + base)    = r;
        float4 dv = make_float4(rsqrtf((float)(c.x + 1)), rsqrtf((float)(c.y + 1)),
                                rsqrtf((float)(c.z + 1)), rsqrtf((float)(c.w + 1)));
        *(float4*)(dinv + base) = dv;
    } else {
        int rr[4] = {off, off + s0, off + s1, off + s2};
        int* cp = (int*)&c;
        for (int j = 0; j < 4; j++)
            if (base + j < n) {
                rowptr[base + j] = rr[j];
                cur[base + j]    = rr[j];
                dinv[base + j]   = rsqrtf((float)(cp[j] + 1));
            }
    }
}

// ---------------------------------------------------------------------------
// CSR fill
// ---------------------------------------------------------------------------
__global__ void k_fill(const int* __restrict__ src, const int* __restrict__ dst,
                       int* __restrict__ cur, int* __restrict__ col, int E) {
    int i = (blockIdx.x * blockDim.x + threadIdx.x) * 4;
    if (i + 3 < E && ((((size_t)src) & 15) == 0) && ((((size_t)dst) & 15) == 0)) {
        int4 s = *(const int4*)(src + i);
        int4 d = *(const int4*)(dst + i);
        col[atomicAdd(&cur[d.x], 1)] = s.x;
        col[atomicAdd(&cur[d.y], 1)] = s.y;
        col[atomicAdd(&cur[d.z], 1)] = s.z;
        col[atomicAdd(&cur[d.w], 1)] = s.w;
    } else {
        for (int j = 0; j < 4; j++)
            if (i + j < E) col[atomicAdd(&cur[dst[i + j]], 1)] = src[i + j];
    }
}

// ---------------------------------------------------------------------------
// W prep: split fp32 W[k][n] into bf16 hi/lo, transposed to Bt[n][k] K-major,
// SW128-swizzled, two K-halves. Layout matches the GEMM smem B image exactly.
// ---------------------------------------------------------------------------
__global__ void k_wprep(const float* __restrict__ W, uint8_t* __restrict__ wb) {
    int idx = blockIdx.x * blockDim.x + threadIdx.x;   // 0..16383
    int nn = idx & 127;           // output col -> Bt row
    int k  = idx >> 7;            // input dim  -> Bt col
    float v = W[k * DD + nn];
    __nv_bfloat16 hi = __float2bfloat16(v);
    __nv_bfloat16 lo = __float2bfloat16(v - __bfloat162float(hi));
    int half = k >> 6, kk = k & 63;
    uint32_t off = swz128((uint32_t)(nn * 128 + kk * 2));
    *(__nv_bfloat16*)(wb + half * 32768 + off)         = hi;
    *(__nv_bfloat16*)(wb + half * 32768 + 16384 + off) = lo;
}

// ---------------------------------------------------------------------------
// Tensor-core GEMM via mma.sync (split bf16, fp32 accum):
//   C[r,:] = dinv[r] * (A[r,:] @ W)
// CTA = 128 rows x 128 cols. 8 warps: warp w -> rows (w&3)*32..+32, cols
// (w>>2)*64..+64 (2 m-tiles x 8 n-tiles of m16n8k16). K processed in two
// 64-halves staged in smem (SW128).
// Smem per half: Ahi[128][64] @0, Alo @16K, Bhi(Bt[128][64]) @32K, Blo @48K.
// ---------------------------------------------------------------------------
static const uint32_t GEMM_SMEM = 65536;

__global__ void __launch_bounds__(256)
k_gemm_mma(const float* __restrict__ A, const uint8_t* __restrict__ wb,
           const float* __restrict__ dinv, float* __restrict__ C, int n) {
    extern __shared__ char sm[];
    uint32_t sbase = smem_u32(sm);
    int tid  = threadIdx.x;
    int wid  = tid >> 5, lane = tid & 31;
    int row0 = blockIdx.x * 128;

    int mrow0 = (wid & 3) * 32;      // warp row base within tile
    int ncol0 = (wid >> 2) * 64;     // warp col base within tile

    float acc[2][8][4];
#pragma unroll
    for (int i = 0; i < 2; i++)
#pragma unroll
        for (int j = 0; j < 8; j++)
#pragma unroll
            for (int q = 0; q < 4; q++) acc[i][j][q] = 0.0f;

    const float4* A4 = (const float4*)A;

    for (int kh = 0; kh < 2; kh++) {
        // ---- stage B: 32KB pre-baked copy
        const float4* wb4 = (const float4*)(wb + kh * 32768);
#pragma unroll
        for (int t = 0; t < 8; t++) {
            int i = tid + t * 256;                     // 0..2047 float4
            *(float4*)(sm + 32768 + i * 16) = wb4[i];
        }
        // ---- stage A: load fp32, split to bf16 hi/lo, swizzled store
#pragma unroll
        for (int t = 0; t < 8; t++) {
            int i  = tid + t * 256;                    // 0..2047
            int m  = i >> 4;                           // row in tile
            int f4 = i & 15;                           // float4 idx in 64-k half
            int gr = row0 + m;
            float4 v = (gr < n) ? A4[(size_t)gr * 32 + kh * 16 + f4]
                                : make_float4(0.f, 0.f, 0.f, 0.f);
            __nv_bfloat16 hx = __float2bfloat16(v.x);
            __nv_bfloat16 hy = __float2bfloat16(v.y);
            __nv_bfloat16 hz = __float2bfloat16(v.z);
            __nv_bfloat16 hw = __float2bfloat16(v.w);
            __nv_bfloat162 h0, h1, l0, l1;
            h0.x = hx; h0.y = hy; h1.x = hz; h1.y = hw;
            l0.x = __float2bfloat16(v.x - __bfloat162float(hx));
            l0.y = __float2bfloat16(v.y - __bfloat162float(hy));
            l1.x = __float2bfloat16(v.z - __bfloat162float(hz));
            l1.y = __float2bfloat16(v.w - __bfloat162float(hw));
            uint32_t off = swz128((uint32_t)(m * 128 + f4 * 8));
            *(__nv_bfloat162*)(sm + off)             = h0;
            *(__nv_bfloat162*)(sm + off + 4)         = h1;
            *(__nv_bfloat162*)(sm + 16384 + off)     = l0;
            *(__nv_bfloat162*)(sm + 16384 + off + 4) = l1;
        }
        __syncthreads();

        // ---- MMA over 4 k16 steps in this half
#pragma unroll
        for (int k16 = 0; k16 < 4; k16++) {
            int kbyte = k16 * 32;
            uint32_t afh[2][4], afl[2][4];
#pragma unroll
            for (int mt = 0; mt < 2; mt++) {
                // ldmatrix.x4 lane->matrix-row address mapping
                int mrow = mrow0 + mt * 16 + (lane & 7) + ((lane & 8) ? 8 : 0);
                int kb   = kbyte + ((lane & 16) ? 16 : 0);
                uint32_t a = sbase + swz128((uint32_t)(mrow * 128 + kb));
                ldsm_x4(afh[mt][0], afh[mt][1], afh[mt][2], afh[mt][3], a);
                ldsm_x4(afl[mt][0], afl[mt][1], afl[mt][2], afl[mt][3], a + 16384);
            }
#pragma unroll
            for (int nt = 0; nt < 8; nt++) {
                int nrow = ncol0 + nt * 8 + (lane & 7);
                int kb   = kbyte + ((lane & 8) ? 16 : 0);
                uint32_t baddr = sbase + 32768 + swz128((uint32_t)(nrow * 128 + kb));
                uint32_t bh0, bh1, bl0, bl1;
                ldsm_x2(bh0, bh1, baddr);
                ldsm_x2(bl0, bl1, baddr + 16384);
#pragma unroll
                for (int mt = 0; mt < 2; mt++) {
                    mma_bf16(acc[mt][nt][0], acc[mt][nt][1], acc[mt][nt][2], acc[mt][nt][3],
                             afh[mt][0], afh[mt][1], afh[mt][2], afh[mt][3], bh0, bh1);
                    mma_bf16(acc[mt][nt][0], acc[mt][nt][1], acc[mt][nt][2], acc[mt][nt][3],
                             afh[mt][0], afh[mt][1], afh[mt][2], afh[mt][3], bl0, bl1);
                    mma_bf16(acc[mt][nt][0], acc[mt][nt][1], acc[mt][nt][2], acc[mt][nt][3],
                             afl[mt][0], afl[mt][1], afl[mt][2], afl[mt][3], bh0, bh1);
                }
            }
        }
        __syncthreads();
    }

    // ---- epilogue: dinv scale + store
#pragma unroll
    for (int mt = 0; mt < 2; mt++) {
        int r1 = row0 + mrow0 + mt * 16 + (lane >> 2);
        int r2 = r1 + 8;
        float s1 = (r1 < n) ? dinv[r1] : 0.f;
        float s2 = (r2 < n) ? dinv[r2] : 0.f;
#pragma unroll
        for (int nt = 0; nt < 8; nt++) {
            int col = ncol0 + nt * 8 + ((lane & 3) << 1);
            if (r1 < n)
                *(float2*)(C + (size_t)r1 * DD + col) =
                    make_float2(acc[mt][nt][0] * s1, acc[mt][nt][1] * s1);
            if (r2 < n)
                *(float2*)(C + (size_t)r2 * DD + col) =
                    make_float2(acc[mt][nt][2] * s2, acc[mt][nt][3] * s2);
        }
    }
}

// ---------------------------------------------------------------------------
// Fused CSR gather + self-loop + bias + ELU. One warp per dst node.
// ---------------------------------------------------------------------------
__device__ __forceinline__ float eluf(float x) { return x > 0.0f ? x : expm1f(x); }

__global__ __launch_bounds__(256) void k_gather(const float* __restrict__ hp,
                                                const int* __restrict__ rowptr,
                                                const int* __restrict__ colv,
                                                const float* __restrict__ dinv,
                                                const float* __restrict__ b,
                                                float* __restrict__ outp, int n) {
    int d    = blockIdx.x * 8 + (threadIdx.x >> 5);
    int lane = threadIdx.x & 31;
    if (d >= n) return;

    const float4* hp4 = (const float4*)hp;

    int start = rowptr[d];
    int end   = rowptr[d + 1];

    float4 acc = hp4[(size_t)d * 32 + lane];   // self-loop

    for (int base = start; base < end; base += 32) {
        int cnt  = min(32, end - base);
        int sidx = (base + lane < end) ? colv[base + lane] : 0;
        int j = 0;
        for (; j + 4 <= cnt; j += 4) {
            int s0 = __shfl_sync(0xffffffffu, sidx, j);
            int s1 = __shfl_sync(0xffffffffu, sidx, j + 1);
            int s2 = __shfl_sync(0xffffffffu, sidx, j + 2);
            int s3 = __shfl_sync(0xffffffffu, sidx, j + 3);
            float4 v0 = hp4[(size_t)s0 * 32 + lane];
            float4 v1 = hp4[(size_t)s1 * 32 + lane];
            float4 v2 = hp4[(size_t)s2 * 32 + lane];
            float4 v3 = hp4[(size_t)s3 * 32 + lane];
            acc.x += v0.x + v1.x + v2.x + v3.x;
            acc.y += v0.y + v1.y + v2.y + v3.y;
            acc.z += v0.z + v1.z + v2.z + v3.z;
            acc.w += v0.w + v1.w + v2.w + v3.w;
        }
        for (; j < cnt; j++) {
            int s    = __shfl_sync(0xffffffffu, sidx, j);
            float4 v = hp4[(size_t)s * 32 + lane];
            acc.x += v.x; acc.y += v.y; acc.z += v.z; acc.w += v.w;
        }
    }

    float w   = dinv[d];
    float4 bb = ((const float4*)b)[lane];
    acc.x = eluf(acc.x * w + bb.x);
    acc.y = eluf(acc.y * w + bb.y);
    acc.z = eluf(acc.z * w + bb.z);
    acc.w = eluf(acc.w * w + bb.w);
    ((float4*)outp)[(size_t)d * 32 + lane] = acc;
}

// ---------------------------------------------------------------------------
// Launch
// ---------------------------------------------------------------------------
extern "C" void kernel_launch(void* const* d_in, const int* in_sizes, int n_in,
                              void* d_out, int out_size) {
    const float* x  = (const float*)d_in[0];
    const int*   ei = (const int*)d_in[1];
    const float* W1 = (const float*)d_in[2];
    const float* b1 = (const float*)d_in[3];
    const float* W2 = (const float*)d_in[4];
    const float* b2 = (const float*)d_in[5];
    float* out = (float*)d_out;

    int N = in_sizes[0] / DD;
    int E = in_sizes[1] / 2;
    const int* src = ei;
    const int* dst = ei + E;

    float *dinv, *buf1, *buf2;
    int *cnt, *rowptr, *cur, *col, *part;
    uint8_t* wb;
    cudaGetSymbolAddress((void**)&dinv, g_dinv);
    cudaGetSymbolAddress((void**)&buf1, g_buf1);
    cudaGetSymbolAddress((void**)&buf2, g_buf2);
    cudaGetSymbolAddress((void**)&cnt, g_cnt);
    cudaGetSymbolAddress((void**)&rowptr, g_rowptr);
    cudaGetSymbolAddress((void**)&cur, g_cur);
    cudaGetSymbolAddress((void**)&col, g_col);
    cudaGetSymbolAddress((void**)&part, g_part);
    cudaGetSymbolAddress((void**)&wb, g_wb);

    cudaFuncSetAttribute(k_gemm_mma, cudaFuncAttributeMaxDynamicSharedMemorySize,
                         GEMM_SMEM);

    const int T  = 256;
    int nb       = (N + 1023) / 1024;
    int egrid4   = (E / 4 + T - 1) / T;

    // CSR build + normalization
    cudaMemsetAsync(cnt, 0, (size_t)N * sizeof(int));
    k_hist<<<egrid4, T>>>(dst, cnt, E);
    k_scan_partial<<<nb, T>>>(cnt, part, N);
    k_scan_tops<<<1, 256>>>(part, rowptr + N, nb);
    k_scan_down<<<nb, T>>>(cnt, part, rowptr, cur, dinv, N);
    k_fill<<<egrid4, T>>>(src, dst, cur, col, E);

    int gemm_grid   = (N + 127) / 128;
    int gather_grid = (N + 7) / 8;

    // Layer 1
    k_wprep<<<64, 256>>>(W1, wb);
    k_gemm_mma<<<gemm_grid, 256, GEMM_SMEM>>>(x, wb, dinv, buf1, N);
    k_gather<<<gather_grid, 256>>>(buf1, rowptr, col, dinv, b1, buf2, N);

    // Layer 2
    k_wprep<<<64, 256>>>(W2, wb);
    k_gemm_mma<<<gemm_grid, 256, GEMM_SMEM>>>(buf2, wb, dinv, buf1, N);
    k_gather<<<gather_grid, 256>>>(buf1, rowptr, col, dinv, b2, out, N);
}

// round 6
// speedup vs baseline: 2.5077x; 1.0411x over previous
#include <cuda_runtime.h>
#include <cuda_bf16.h>
#include <cuda_fp16.h>
#include <math.h>
#include <stdint.h>

#define DD   128
#define MAXN 50000
#define MAXE 800000

// Scratch (allocation-free rule: __device__ globals)
__device__ __align__(16) float   g_dinv[MAXN];
__device__ __align__(16) __half  g_hbuf[(size_t)MAXN * DD];  // fp16 messages
__device__ __align__(16) float   g_buf2[(size_t)MAXN * DD];  // fp32 activation
__device__ __align__(16) int     g_cnt[MAXN];
__device__ __align__(16) int     g_rowptr[MAXN + 4];
__device__ __align__(16) int     g_cur[MAXN];
__device__ __align__(16) int     g_col[MAXE];
__device__ __align__(16) int     g_part[256];
// Pre-split/transposed/swizzled W image:
// [kh0: Bhi 16KB | Blo 16KB][kh1: Bhi 16KB | Blo 16KB]  (Bt[n][k] bf16, SW128)
__device__ __align__(16) uint8_t g_wb[65536];

// ---------------------------------------------------------------------------
// Helpers (sm_80+ only: ldmatrix + mma.sync — NO tcgen05, target is sm_103)
// ---------------------------------------------------------------------------
__device__ __forceinline__ uint32_t swz128(uint32_t off) {
    return off ^ ((off >> 3) & 0x70);
}
__device__ __forceinline__ uint32_t smem_u32(const void* p) {
    return (uint32_t)__cvta_generic_to_shared(p);
}

__device__ __forceinline__ void ldsm_x4(uint32_t& r0, uint32_t& r1,
                                        uint32_t& r2, uint32_t& r3, uint32_t addr) {
    asm volatile("ldmatrix.sync.aligned.m8n8.x4.shared.b16 {%0,%1,%2,%3}, [%4];"
                 : "=r"(r0), "=r"(r1), "=r"(r2), "=r"(r3) : "r"(addr));
}
__device__ __forceinline__ void ldsm_x2(uint32_t& r0, uint32_t& r1, uint32_t addr) {
    asm volatile("ldmatrix.sync.aligned.m8n8.x2.shared.b16 {%0,%1}, [%2];"
                 : "=r"(r0), "=r"(r1) : "r"(addr));
}
__device__ __forceinline__ void mma_bf16(float& d0, float& d1, float& d2, float& d3,
                                         uint32_t a0, uint32_t a1, uint32_t a2, uint32_t a3,
                                         uint32_t b0, uint32_t b1) {
    asm volatile(
        "mma.sync.aligned.m16n8k16.row.col.f32.bf16.bf16.f32 "
        "{%0,%1,%2,%3}, {%4,%5,%6,%7}, {%8,%9}, {%0,%1,%2,%3};"
        : "+f"(d0), "+f"(d1), "+f"(d2), "+f"(d3)
        : "r"(a0), "r"(a1), "r"(a2), "r"(a3), "r"(b0), "r"(b1));
}

// ---------------------------------------------------------------------------
// Histogram of dst (4 edges per thread)
// ---------------------------------------------------------------------------
__global__ void k_hist(const int* __restrict__ dst, int* __restrict__ cnt, int E) {
    int i = (blockIdx.x * blockDim.x + threadIdx.x) * 4;
    if (i + 3 < E && ((((size_t)dst) & 15) == 0)) {
        int4 d = *(const int4*)(dst + i);
        atomicAdd(&cnt[d.x], 1);
        atomicAdd(&cnt[d.y], 1);
        atomicAdd(&cnt[d.z], 1);
        atomicAdd(&cnt[d.w], 1);
    } else {
        for (int j = 0; j < 4; j++)
            if (i + j < E) atomicAdd(&cnt[dst[i + j]], 1);
    }
}

// ---------------------------------------------------------------------------
// 3-phase exclusive scan (+ dinv epilogue)
// ---------------------------------------------------------------------------
__global__ __launch_bounds__(256) void k_scan_partial(const int* __restrict__ cnt,
                                                      int* __restrict__ part, int n) {
    __shared__ int sh[8];
    int tid  = threadIdx.x;
    int base = blockIdx.x * 1024 + tid * 4;
    int s = 0;
    if (base + 3 < n) {
        int4 v = *(const int4*)(cnt + base);
        s = v.x + v.y + v.z + v.w;
    } else {
        for (int j = 0; j < 4; j++)
            if (base + j < n) s += cnt[base + j];
    }
#pragma unroll
    for (int o = 16; o; o >>= 1) s += __shfl_down_sync(0xffffffffu, s, o);
    if ((tid & 31) == 0) sh[tid >> 5] = s;
    __syncthreads();
    if (tid < 8) {
        s = sh[tid];
#pragma unroll
        for (int o = 4; o; o >>= 1) s += __shfl_down_sync(0x000000ffu, s, o);
        if (tid == 0) part[blockIdx.x] = s;
    }
}

__global__ void k_scan_tops(int* __restrict__ part, int* __restrict__ total, int nb) {
    __shared__ int sh[256];
    int t = threadIdx.x;
    int v = (t < nb) ? part[t] : 0;
    sh[t] = v;
    __syncthreads();
    for (int o = 1; o < 256; o <<= 1) {
        int u = (t >= o) ? sh[t - o] : 0;
        __syncthreads();
        sh[t] += u;
        __syncthreads();
    }
    if (t < nb) part[t] = sh[t] - v;
    if (t == 255) *total = sh[255];
}

__global__ __launch_bounds__(256) void k_scan_down(const int* __restrict__ cnt,
                                                   const int* __restrict__ part,
                                                   int* __restrict__ rowptr,
                                                   int* __restrict__ cur,
                                                   float* __restrict__ dinv, int n) {
    __shared__ int wsum[8];
    int tid  = threadIdx.x;
    int lane = tid & 31, wid = tid >> 5;
    int base = blockIdx.x * 1024 + tid * 4;

    int4 c = make_int4(0, 0, 0, 0);
    if (base + 3 < n) c = *(const int4*)(cnt + base);
    else {
        int* cp = (int*)&c;
        for (int j = 0; j < 4; j++) cp[j] = (base + j < n) ? cnt[base + j] : 0;
    }
    int s0 = c.x, s1 = s0 + c.y, s2 = s1 + c.z, s3 = s2 + c.w;
    int ts = s3, sc = ts;
#pragma unroll
    for (int o = 1; o < 32; o <<= 1) {
        int u = __shfl_up_sync(0xffffffffu, sc, o);
        if (lane >= o) sc += u;
    }
    if (lane == 31) wsum[wid] = sc;
    __syncthreads();
    if (wid == 0) {
        int w = (lane < 8) ? wsum[lane] : 0;
#pragma unroll
        for (int o = 1; o < 8; o <<= 1) {
            int u = __shfl_up_sync(0xffffffffu, w, o);
            if (lane >= o) w += u;
        }
        if (lane < 8) wsum[lane] = w;
    }
    __syncthreads();

    int off = part[blockIdx.x] + (wid ? wsum[wid - 1] : 0) + (sc - ts);
    if (base + 3 < n) {
        int4 r = make_int4(off, off + s0, off + s1, off + s2);
        *(int4*)(rowptr + base) = r;
        *(int4*)(cur + base)    = r;
        float4 dv = make_float4(rsqrtf((float)(c.x + 1)), rsqrtf((float)(c.y + 1)),
                                rsqrtf((float)(c.z + 1)), rsqrtf((float)(c.w + 1)));
        *(float4*)(dinv + base) = dv;
    } else {
        int rr[4] = {off, off + s0, off + s1, off + s2};
        int* cp = (int*)&c;
        for (int j = 0; j < 4; j++)
            if (base + j < n) {
                rowptr[base + j] = rr[j];
                cur[base + j]    = rr[j];
                dinv[base + j]   = rsqrtf((float)(cp[j] + 1));
            }
    }
}

// ---------------------------------------------------------------------------
// CSR fill
// ---------------------------------------------------------------------------
__global__ void k_fill(const int* __restrict__ src, const int* __restrict__ dst,
                       int* __restrict__ cur, int* __restrict__ col, int E) {
    int i = (blockIdx.x * blockDim.x + threadIdx.x) * 4;
    if (i + 3 < E && ((((size_t)src) & 15) == 0) && ((((size_t)dst) & 15) == 0)) {
        int4 s = *(const int4*)(src + i);
        int4 d = *(const int4*)(dst + i);
        col[atomicAdd(&cur[d.x], 1)] = s.x;
        col[atomicAdd(&cur[d.y], 1)] = s.y;
        col[atomicAdd(&cur[d.z], 1)] = s.z;
        col[atomicAdd(&cur[d.w], 1)] = s.w;
    } else {
        for (int j = 0; j < 4; j++)
            if (i + j < E) col[atomicAdd(&cur[dst[i + j]], 1)] = src[i + j];
    }
}

// ---------------------------------------------------------------------------
// W prep: split fp32 W[k][n] into bf16 hi/lo, transposed to Bt[n][k] K-major,
// SW128-swizzled, two K-halves. Layout matches the GEMM smem B image exactly.
// ---------------------------------------------------------------------------
__global__ void k_wprep(const float* __restrict__ W, uint8_t* __restrict__ wb) {
    int idx = blockIdx.x * blockDim.x + threadIdx.x;   // 0..16383
    int nn = idx & 127;           // output col -> Bt row
    int k  = idx >> 7;            // input dim  -> Bt col
    float v = W[k * DD + nn];
    __nv_bfloat16 hi = __float2bfloat16(v);
    __nv_bfloat16 lo = __float2bfloat16(v - __bfloat162float(hi));
    int half = k >> 6, kk = k & 63;
    uint32_t off = swz128((uint32_t)(nn * 128 + kk * 2));
    *(__nv_bfloat16*)(wb + half * 32768 + off)         = hi;
    *(__nv_bfloat16*)(wb + half * 32768 + 16384 + off) = lo;
}

// ---------------------------------------------------------------------------
// Tensor-core GEMM via mma.sync (split bf16, fp32 accum), fp16 output:
//   Ch[r,:] = (half) dinv[r] * (A[r,:] @ W)
// ---------------------------------------------------------------------------
static const uint32_t GEMM_SMEM = 65536;

__global__ void __launch_bounds__(256)
k_gemm_mma(const float* __restrict__ A, const uint8_t* __restrict__ wb,
           const float* __restrict__ dinv, __half* __restrict__ Ch, int n) {
    extern __shared__ char sm[];
    uint32_t sbase = smem_u32(sm);
    int tid  = threadIdx.x;
    int wid  = tid >> 5, lane = tid & 31;
    int row0 = blockIdx.x * 128;

    int mrow0 = (wid & 3) * 32;      // warp row base within tile
    int ncol0 = (wid >> 2) * 64;     // warp col base within tile

    float acc[2][8][4];
#pragma unroll
    for (int i = 0; i < 2; i++)
#pragma unroll
        for (int j = 0; j < 8; j++)
#pragma unroll
            for (int q = 0; q < 4; q++) acc[i][j][q] = 0.0f;

    const float4* A4 = (const float4*)A;

    for (int kh = 0; kh < 2; kh++) {
        // ---- stage B: 32KB pre-baked copy
        const float4* wb4 = (const float4*)(wb + kh * 32768);
#pragma unroll
        for (int t = 0; t < 8; t++) {
            int i = tid + t * 256;                     // 0..2047 float4
            *(float4*)(sm + 32768 + i * 16) = wb4[i];
        }
        // ---- stage A: load fp32, split to bf16 hi/lo, swizzled store
#pragma unroll
        for (int t = 0; t < 8; t++) {
            int i  = tid + t * 256;                    // 0..2047
            int m  = i >> 4;                           // row in tile
            int f4 = i & 15;                           // float4 idx in 64-k half
            int gr = row0 + m;
            float4 v = (gr < n) ? A4[(size_t)gr * 32 + kh * 16 + f4]
                                : make_float4(0.f, 0.f, 0.f, 0.f);
            __nv_bfloat16 hx = __float2bfloat16(v.x);
            __nv_bfloat16 hy = __float2bfloat16(v.y);
            __nv_bfloat16 hz = __float2bfloat16(v.z);
            __nv_bfloat16 hw = __float2bfloat16(v.w);
            __nv_bfloat162 h0, h1, l0, l1;
            h0.x = hx; h0.y = hy; h1.x = hz; h1.y = hw;
            l0.x = __float2bfloat16(v.x - __bfloat162float(hx));
            l0.y = __float2bfloat16(v.y - __bfloat162float(hy));
            l1.x = __float2bfloat16(v.z - __bfloat162float(hz));
            l1.y = __float2bfloat16(v.w - __bfloat162float(hw));
            uint32_t off = swz128((uint32_t)(m * 128 + f4 * 8));
            *(__nv_bfloat162*)(sm + off)             = h0;
            *(__nv_bfloat162*)(sm + off + 4)         = h1;
            *(__nv_bfloat162*)(sm + 16384 + off)     = l0;
            *(__nv_bfloat162*)(sm + 16384 + off + 4) = l1;
        }
        __syncthreads();

        // ---- MMA over 4 k16 steps in this half
#pragma unroll
        for (int k16 = 0; k16 < 4; k16++) {
            int kbyte = k16 * 32;
            uint32_t afh[2][4], afl[2][4];
#pragma unroll
            for (int mt = 0; mt < 2; mt++) {
                int mrow = mrow0 + mt * 16 + (lane & 7) + ((lane & 8) ? 8 : 0);
                int kb   = kbyte + ((lane & 16) ? 16 : 0);
                uint32_t a = sbase + swz128((uint32_t)(mrow * 128 + kb));
                ldsm_x4(afh[mt][0], afh[mt][1], afh[mt][2], afh[mt][3], a);
                ldsm_x4(afl[mt][0], afl[mt][1], afl[mt][2], afl[mt][3], a + 16384);
            }
#pragma unroll
            for (int nt = 0; nt < 8; nt++) {
                int nrow = ncol0 + nt * 8 + (lane & 7);
                int kb   = kbyte + ((lane & 8) ? 16 : 0);
                uint32_t baddr = sbase + 32768 + swz128((uint32_t)(nrow * 128 + kb));
                uint32_t bh0, bh1, bl0, bl1;
                ldsm_x2(bh0, bh1, baddr);
                ldsm_x2(bl0, bl1, baddr + 16384);
#pragma unroll
                for (int mt = 0; mt < 2; mt++) {
                    mma_bf16(acc[mt][nt][0], acc[mt][nt][1], acc[mt][nt][2], acc[mt][nt][3],
                             afh[mt][0], afh[mt][1], afh[mt][2], afh[mt][3], bh0, bh1);
                    mma_bf16(acc[mt][nt][0], acc[mt][nt][1], acc[mt][nt][2], acc[mt][nt][3],
                             afh[mt][0], afh[mt][1], afh[mt][2], afh[mt][3], bl0, bl1);
                    mma_bf16(acc[mt][nt][0], acc[mt][nt][1], acc[mt][nt][2], acc[mt][nt][3],
                             afl[mt][0], afl[mt][1], afl[mt][2], afl[mt][3], bh0, bh1);
                }
            }
        }
        __syncthreads();
    }

    // ---- epilogue: dinv scale + fp16 store
#pragma unroll
    for (int mt = 0; mt < 2; mt++) {
        int r1 = row0 + mrow0 + mt * 16 + (lane >> 2);
        int r2 = r1 + 8;
        float s1 = (r1 < n) ? dinv[r1] : 0.f;
        float s2 = (r2 < n) ? dinv[r2] : 0.f;
#pragma unroll
        for (int nt = 0; nt < 8; nt++) {
            int col = ncol0 + nt * 8 + ((lane & 3) << 1);
            if (r1 < n)
                *(__half2*)(Ch + (size_t)r1 * DD + col) =
                    __floats2half2_rn(acc[mt][nt][0] * s1, acc[mt][nt][1] * s1);
            if (r2 < n)
                *(__half2*)(Ch + (size_t)r2 * DD + col) =
                    __floats2half2_rn(acc[mt][nt][2] * s2, acc[mt][nt][3] * s2);
        }
    }
}

// ---------------------------------------------------------------------------
// Fused CSR gather + self-loop + bias + ELU. One warp per dst node.
// fp16 messages in, fp32 accumulate, fp32 out. Lane l owns 4 halves (uint2).
// ---------------------------------------------------------------------------
__device__ __forceinline__ float eluf(float x) { return x > 0.0f ? x : expm1f(x); }

__device__ __forceinline__ void acc_h4(float4& acc, uint2 u) {
    float2 f0 = __half22float2(*(const __half2*)&u.x);
    float2 f1 = __half22float2(*(const __half2*)&u.y);
    acc.x += f0.x; acc.y += f0.y; acc.z += f1.x; acc.w += f1.y;
}

__global__ __launch_bounds__(256) void k_gather(const __half* __restrict__ hp,
                                                const int* __restrict__ rowptr,
                                                const int* __restrict__ colv,
                                                const float* __restrict__ dinv,
                                                const float* __restrict__ b,
                                                float* __restrict__ outp, int n) {
    int d    = blockIdx.x * 8 + (threadIdx.x >> 5);
    int lane = threadIdx.x & 31;
    if (d >= n) return;

    const uint2* hp2 = (const uint2*)hp;   // 32 uint2 (= 4 halves each) per row

    int start = rowptr[d];
    int end   = rowptr[d + 1];

    float4 acc = make_float4(0.f, 0.f, 0.f, 0.f);
    acc_h4(acc, hp2[(size_t)d * 32 + lane]);   // self-loop

    for (int base = start; base < end; base += 32) {
        int cnt  = min(32, end - base);
        int sidx = (base + lane < end) ? colv[base + lane] : 0;
        int j = 0;
        for (; j + 4 <= cnt; j += 4) {
            int s0 = __shfl_sync(0xffffffffu, sidx, j);
            int s1 = __shfl_sync(0xffffffffu, sidx, j + 1);
            int s2 = __shfl_sync(0xffffffffu, sidx, j + 2);
            int s3 = __shfl_sync(0xffffffffu, sidx, j + 3);
            uint2 u0 = hp2[(size_t)s0 * 32 + lane];
            uint2 u1 = hp2[(size_t)s1 * 32 + lane];
            uint2 u2 = hp2[(size_t)s2 * 32 + lane];
            uint2 u3 = hp2[(size_t)s3 * 32 + lane];
            acc_h4(acc, u0);
            acc_h4(acc, u1);
            acc_h4(acc, u2);
            acc_h4(acc, u3);
        }
        for (; j < cnt; j++) {
            int s = __shfl_sync(0xffffffffu, sidx, j);
            acc_h4(acc, hp2[(size_t)s * 32 + lane]);
        }
    }

    float w = dinv[d];
    // lane owns cols [lane*4, lane*4+4)
    float4 bb = ((const float4*)b)[lane];
    acc.x = eluf(acc.x * w + bb.x);
    acc.y = eluf(acc.y * w + bb.y);
    acc.z = eluf(acc.z * w + bb.z);
    acc.w = eluf(acc.w * w + bb.w);
    ((float4*)outp)[(size_t)d * 32 + lane] = acc;
}

// ---------------------------------------------------------------------------
// Launch
// ---------------------------------------------------------------------------
extern "C" void kernel_launch(void* const* d_in, const int* in_sizes, int n_in,
                              void* d_out, int out_size) {
    const float* x  = (const float*)d_in[0];
    const int*   ei = (const int*)d_in[1];
    const float* W1 = (const float*)d_in[2];
    const float* b1 = (const float*)d_in[3];
    const float* W2 = (const float*)d_in[4];
    const float* b2 = (const float*)d_in[5];
    float* out = (float*)d_out;

    int N = in_sizes[0] / DD;
    int E = in_sizes[1] / 2;
    const int* src = ei;
    const int* dst = ei + E;

    float *dinv, *buf2;
    __half* hbuf;
    int *cnt, *rowptr, *cur, *col, *part;
    uint8_t* wb;
    cudaGetSymbolAddress((void**)&dinv, g_dinv);
    cudaGetSymbolAddress((void**)&hbuf, g_hbuf);
    cudaGetSymbolAddress((void**)&buf2, g_buf2);
    cudaGetSymbolAddress((void**)&cnt, g_cnt);
    cudaGetSymbolAddress((void**)&rowptr, g_rowptr);
    cudaGetSymbolAddress((void**)&cur, g_cur);
    cudaGetSymbolAddress((void**)&col, g_col);
    cudaGetSymbolAddress((void**)&part, g_part);
    cudaGetSymbolAddress((void**)&wb, g_wb);

    cudaFuncSetAttribute(k_gemm_mma, cudaFuncAttributeMaxDynamicSharedMemorySize,
                         GEMM_SMEM);

    const int T  = 256;
    int nb       = (N + 1023) / 1024;
    int egrid4   = (E / 4 + T - 1) / T;

    // CSR build + normalization
    cudaMemsetAsync(cnt, 0, (size_t)N * sizeof(int));
    k_hist<<<egrid4, T>>>(dst, cnt, E);
    k_scan_partial<<<nb, T>>>(cnt, part, N);
    k_scan_tops<<<1, 256>>>(part, rowptr + N, nb);
    k_scan_down<<<nb, T>>>(cnt, part, rowptr, cur, dinv, N);
    k_fill<<<egrid4, T>>>(src, dst, cur, col, E);

    int gemm_grid   = (N + 127) / 128;
    int gather_grid = (N + 7) / 8;

    // Layer 1
    k_wprep<<<64, 256>>>(W1, wb);
    k_gemm_mma<<<gemm_grid, 256, GEMM_SMEM>>>(x, wb, dinv, hbuf, N);
    k_gather<<<gather_grid, 256>>>(hbuf, rowptr, col, dinv, b1, buf2, N);

    // Layer 2
    k_wprep<<<64, 256>>>(W2, wb);
    k_gemm_mma<<<gemm_grid, 256, GEMM_SMEM>>>(buf2, wb, dinv, hbuf, N);
    k_gather<<<gather_grid, 256>>>(hbuf, rowptr, col, dinv, b2, out, N);
}

// round 7
// speedup vs baseline: 2.5172x; 1.0038x over previous
#include <cuda_runtime.h>
#include <cuda_bf16.h>
#include <cuda_fp16.h>
#include <math.h>
#include <stdint.h>

#define DD   128
#define MAXN 50000
#define MAXE 800000

// Scratch (allocation-free rule: __device__ globals)
__device__ __align__(16) float   g_dinv[MAXN];
__device__ __align__(16) __half  g_hbuf[(size_t)MAXN * DD];  // fp16 messages
__device__ __align__(16) float   g_buf2[(size_t)MAXN * DD];  // fp32 activation
__device__ __align__(16) int     g_cnt[MAXN];
__device__ __align__(16) int     g_rowptr[MAXN + 4];
__device__ __align__(16) int     g_cur[MAXN];
__device__ __align__(16) int     g_col[MAXE];
__device__ __align__(16) int     g_part[256];
// Pre-split/transposed/swizzled W image:
// [kh0: Bhi 16KB | Blo 16KB][kh1: Bhi 16KB | Blo 16KB]  (Bt[n][k] bf16, SW128)
__device__ __align__(16) uint8_t g_wb[65536];

// ---------------------------------------------------------------------------
// Helpers (sm_80+ only: ldmatrix + mma.sync — NO tcgen05, target is sm_103)
// ---------------------------------------------------------------------------
__device__ __forceinline__ uint32_t swz128(uint32_t off) {
    return off ^ ((off >> 3) & 0x70);
}
__device__ __forceinline__ uint32_t smem_u32(const void* p) {
    return (uint32_t)__cvta_generic_to_shared(p);
}

__device__ __forceinline__ void ldsm_x4(uint32_t& r0, uint32_t& r1,
                                        uint32_t& r2, uint32_t& r3, uint32_t addr) {
    asm volatile("ldmatrix.sync.aligned.m8n8.x4.shared.b16 {%0,%1,%2,%3}, [%4];"
                 : "=r"(r0), "=r"(r1), "=r"(r2), "=r"(r3) : "r"(addr));
}
__device__ __forceinline__ void ldsm_x2(uint32_t& r0, uint32_t& r1, uint32_t addr) {
    asm volatile("ldmatrix.sync.aligned.m8n8.x2.shared.b16 {%0,%1}, [%2];"
                 : "=r"(r0), "=r"(r1) : "r"(addr));
}
__device__ __forceinline__ void mma_bf16(float& d0, float& d1, float& d2, float& d3,
                                         uint32_t a0, uint32_t a1, uint32_t a2, uint32_t a3,
                                         uint32_t b0, uint32_t b1) {
    asm volatile(
        "mma.sync.aligned.m16n8k16.row.col.f32.bf16.bf16.f32 "
        "{%0,%1,%2,%3}, {%4,%5,%6,%7}, {%8,%9}, {%0,%1,%2,%3};"
        : "+f"(d0), "+f"(d1), "+f"(d2), "+f"(d3)
        : "r"(a0), "r"(a1), "r"(a2), "r"(a3), "r"(b0), "r"(b1));
}

// ---------------------------------------------------------------------------
// Histogram of dst (4 edges per thread)
// ---------------------------------------------------------------------------
__global__ void k_hist(const int* __restrict__ dst, int* __restrict__ cnt, int E) {
    int i = (blockIdx.x * blockDim.x + threadIdx.x) * 4;
    if (i + 3 < E && ((((size_t)dst) & 15) == 0)) {
        int4 d = *(const int4*)(dst + i);
        atomicAdd(&cnt[d.x], 1);
        atomicAdd(&cnt[d.y], 1);
        atomicAdd(&cnt[d.z], 1);
        atomicAdd(&cnt[d.w], 1);
    } else {
        for (int j = 0; j < 4; j++)
            if (i + j < E) atomicAdd(&cnt[dst[i + j]], 1);
    }
}

// ---------------------------------------------------------------------------
// 3-phase exclusive scan (+ dinv epilogue)
// ---------------------------------------------------------------------------
__global__ __launch_bounds__(256) void k_scan_partial(const int* __restrict__ cnt,
                                                      int* __restrict__ part, int n) {
    __shared__ int sh[8];
    int tid  = threadIdx.x;
    int base = blockIdx.x * 1024 + tid * 4;
    int s = 0;
    if (base + 3 < n) {
        int4 v = *(const int4*)(cnt + base);
        s = v.x + v.y + v.z + v.w;
    } else {
        for (int j = 0; j < 4; j++)
            if (base + j < n) s += cnt[base + j];
    }
#pragma unroll
    for (int o = 16; o; o >>= 1) s += __shfl_down_sync(0xffffffffu, s, o);
    if ((tid & 31) == 0) sh[tid >> 5] = s;
    __syncthreads();
    if (tid < 8) {
        s = sh[tid];
#pragma unroll
        for (int o = 4; o; o >>= 1) s += __shfl_down_sync(0x000000ffu, s, o);
        if (tid == 0) part[blockIdx.x] = s;
    }
}

__global__ void k_scan_tops(int* __restrict__ part, int* __restrict__ total, int nb) {
    __shared__ int sh[256];
    int t = threadIdx.x;
    int v = (t < nb) ? part[t] : 0;
    sh[t] = v;
    __syncthreads();
    for (int o = 1; o < 256; o <<= 1) {
        int u = (t >= o) ? sh[t - o] : 0;
        __syncthreads();
        sh[t] += u;
        __syncthreads();
    }
    if (t < nb) part[t] = sh[t] - v;
    if (t == 255) *total = sh[255];
}

__global__ __launch_bounds__(256) void k_scan_down(const int* __restrict__ cnt,
                                                   const int* __restrict__ part,
                                                   int* __restrict__ rowptr,
                                                   int* __restrict__ cur,
                                                   float* __restrict__ dinv, int n) {
    __shared__ int wsum[8];
    int tid  = threadIdx.x;
    int lane = tid & 31, wid = tid >> 5;
    int base = blockIdx.x * 1024 + tid * 4;

    int4 c = make_int4(0, 0, 0, 0);
    if (base + 3 < n) c = *(const int4*)(cnt + base);
    else {
        int* cp = (int*)&c;
        for (int j = 0; j < 4; j++) cp[j] = (base + j < n) ? cnt[base + j] : 0;
    }
    int s0 = c.x, s1 = s0 + c.y, s2 = s1 + c.z, s3 = s2 + c.w;
    int ts = s3, sc = ts;
#pragma unroll
    for (int o = 1; o < 32; o <<= 1) {
        int u = __shfl_up_sync(0xffffffffu, sc, o);
        if (lane >= o) sc += u;
    }
    if (lane == 31) wsum[wid] = sc;
    __syncthreads();
    if (wid == 0) {
        int w = (lane < 8) ? wsum[lane] : 0;
#pragma unroll
        for (int o = 1; o < 8; o <<= 1) {
            int u = __shfl_up_sync(0xffffffffu, w, o);
            if (lane >= o) w += u;
        }
        if (lane < 8) wsum[lane] = w;
    }
    __syncthreads();

    int off = part[blockIdx.x] + (wid ? wsum[wid - 1] : 0) + (sc - ts);
    if (base + 3 < n) {
        int4 r = make_int4(off, off + s0, off + s1, off + s2);
        *(int4*)(rowptr + base) = r;
        *(int4*)(cur + base)    = r;
        float4 dv = make_float4(rsqrtf((float)(c.x + 1)), rsqrtf((float)(c.y + 1)),
                                rsqrtf((float)(c.z + 1)), rsqrtf((float)(c.w + 1)));
        *(float4*)(dinv + base) = dv;
    } else {
        int rr[4] = {off, off + s0, off + s1, off + s2};
        int* cp = (int*)&c;
        for (int j = 0; j < 4; j++)
            if (base + j < n) {
                rowptr[base + j] = rr[j];
                cur[base + j]    = rr[j];
                dinv[base + j]   = rsqrtf((float)(cp[j] + 1));
            }
    }
}

// ---------------------------------------------------------------------------
// CSR fill
// ---------------------------------------------------------------------------
__global__ void k_fill(const int* __restrict__ src, const int* __restrict__ dst,
                       int* __restrict__ cur, int* __restrict__ col, int E) {
    int i = (blockIdx.x * blockDim.x + threadIdx.x) * 4;
    if (i + 3 < E && ((((size_t)src) & 15) == 0) && ((((size_t)dst) & 15) == 0)) {
        int4 s = *(const int4*)(src + i);
        int4 d = *(const int4*)(dst + i);
        col[atomicAdd(&cur[d.x], 1)] = s.x;
        col[atomicAdd(&cur[d.y], 1)] = s.y;
        col[atomicAdd(&cur[d.z], 1)] = s.z;
        col[atomicAdd(&cur[d.w], 1)] = s.w;
    } else {
        for (int j = 0; j < 4; j++)
            if (i + j < E) col[atomicAdd(&cur[dst[i + j]], 1)] = src[i + j];
    }
}

// ---------------------------------------------------------------------------
// W prep: split fp32 W[k][n] into bf16 hi/lo, transposed to Bt[n][k] K-major,
// SW128-swizzled, two K-halves. Layout matches the GEMM smem B image exactly.
// ---------------------------------------------------------------------------
__global__ void k_wprep(const float* __restrict__ W, uint8_t* __restrict__ wb) {
    int idx = blockIdx.x * blockDim.x + threadIdx.x;   // 0..16383
    int nn = idx & 127;           // output col -> Bt row
    int k  = idx >> 7;            // input dim  -> Bt col
    float v = W[k * DD + nn];
    __nv_bfloat16 hi = __float2bfloat16(v);
    __nv_bfloat16 lo = __float2bfloat16(v - __bfloat162float(hi));
    int half = k >> 6, kk = k & 63;
    uint32_t off = swz128((uint32_t)(nn * 128 + kk * 2));
    *(__nv_bfloat16*)(wb + half * 32768 + off)         = hi;
    *(__nv_bfloat16*)(wb + half * 32768 + 16384 + off) = lo;
}

// ---------------------------------------------------------------------------
// Tensor-core GEMM via mma.sync (split bf16, fp32 accum), fp16 output:
//   Ch[r,:] = (half) dinv[r] * (A[r,:] @ W)
// ---------------------------------------------------------------------------
static const uint32_t GEMM_SMEM = 65536;

__global__ void __launch_bounds__(256)
k_gemm_mma(const float* __restrict__ A, const uint8_t* __restrict__ wb,
           const float* __restrict__ dinv, __half* __restrict__ Ch, int n) {
    extern __shared__ char sm[];
    uint32_t sbase = smem_u32(sm);
    int tid  = threadIdx.x;
    int wid  = tid >> 5, lane = tid & 31;
    int row0 = blockIdx.x * 128;

    int mrow0 = (wid & 3) * 32;      // warp row base within tile
    int ncol0 = (wid >> 2) * 64;     // warp col base within tile

    float acc[2][8][4];
#pragma unroll
    for (int i = 0; i < 2; i++)
#pragma unroll
        for (int j = 0; j < 8; j++)
#pragma unroll
            for (int q = 0; q < 4; q++) acc[i][j][q] = 0.0f;

    const float4* A4 = (const float4*)A;

    for (int kh = 0; kh < 2; kh++) {
        // ---- stage B: 32KB pre-baked copy
        const float4* wb4 = (const float4*)(wb + kh * 32768);
#pragma unroll
        for (int t = 0; t < 8; t++) {
            int i = tid + t * 256;                     // 0..2047 float4
            *(float4*)(sm + 32768 + i * 16) = wb4[i];
        }
        // ---- stage A: load fp32, split to bf16 hi/lo, swizzled store
#pragma unroll
        for (int t = 0; t < 8; t++) {
            int i  = tid + t * 256;                    // 0..2047
            int m  = i >> 4;                           // row in tile
            int f4 = i & 15;                           // float4 idx in 64-k half
            int gr = row0 + m;
            float4 v = (gr < n) ? A4[(size_t)gr * 32 + kh * 16 + f4]
                                : make_float4(0.f, 0.f, 0.f, 0.f);
            __nv_bfloat16 hx = __float2bfloat16(v.x);
            __nv_bfloat16 hy = __float2bfloat16(v.y);
            __nv_bfloat16 hz = __float2bfloat16(v.z);
            __nv_bfloat16 hw = __float2bfloat16(v.w);
            __nv_bfloat162 h0, h1, l0, l1;
            h0.x = hx; h0.y = hy; h1.x = hz; h1.y = hw;
            l0.x = __float2bfloat16(v.x - __bfloat162float(hx));
            l0.y = __float2bfloat16(v.y - __bfloat162float(hy));
            l1.x = __float2bfloat16(v.z - __bfloat162float(hz));
            l1.y = __float2bfloat16(v.w - __bfloat162float(hw));
            uint32_t off = swz128((uint32_t)(m * 128 + f4 * 8));
            *(__nv_bfloat162*)(sm + off)             = h0;
            *(__nv_bfloat162*)(sm + off + 4)         = h1;
            *(__nv_bfloat162*)(sm + 16384 + off)     = l0;
            *(__nv_bfloat162*)(sm + 16384 + off + 4) = l1;
        }
        __syncthreads();

        // ---- MMA over 4 k16 steps in this half
#pragma unroll
        for (int k16 = 0; k16 < 4; k16++) {
            int kbyte = k16 * 32;
            uint32_t afh[2][4], afl[2][4];
#pragma unroll
            for (int mt = 0; mt < 2; mt++) {
                int mrow = mrow0 + mt * 16 + (lane & 7) + ((lane & 8) ? 8 : 0);
                int kb   = kbyte + ((lane & 16) ? 16 : 0);
                uint32_t a = sbase + swz128((uint32_t)(mrow * 128 + kb));
                ldsm_x4(afh[mt][0], afh[mt][1], afh[mt][2], afh[mt][3], a);
                ldsm_x4(afl[mt][0], afl[mt][1], afl[mt][2], afl[mt][3], a + 16384);
            }
#pragma unroll
            for (int nt = 0; nt < 8; nt++) {
                int nrow = ncol0 + nt * 8 + (lane & 7);
                int kb   = kbyte + ((lane & 8) ? 16 : 0);
                uint32_t baddr = sbase + 32768 + swz128((uint32_t)(nrow * 128 + kb));
                uint32_t bh0, bh1, bl0, bl1;
                ldsm_x2(bh0, bh1, baddr);
                ldsm_x2(bl0, bl1, baddr + 16384);
#pragma unroll
                for (int mt = 0; mt < 2; mt++) {
                    mma_bf16(acc[mt][nt][0], acc[mt][nt][1], acc[mt][nt][2], acc[mt][nt][3],
                             afh[mt][0], afh[mt][1], afh[mt][2], afh[mt][3], bh0, bh1);
                    mma_bf16(acc[mt][nt][0], acc[mt][nt][1], acc[mt][nt][2], acc[mt][nt][3],
                             afh[mt][0], afh[mt][1], afh[mt][2], afh[mt][3], bl0, bl1);
                    mma_bf16(acc[mt][nt][0], acc[mt][nt][1], acc[mt][nt][2], acc[mt][nt][3],
                             afl[mt][0], afl[mt][1], afl[mt][2], afl[mt][3], bh0, bh1);
                }
            }
        }
        __syncthreads();
    }

    // ---- epilogue: dinv scale + fp16 store
#pragma unroll
    for (int mt = 0; mt < 2; mt++) {
        int r1 = row0 + mrow0 + mt * 16 + (lane >> 2);
        int r2 = r1 + 8;
        float s1 = (r1 < n) ? dinv[r1] : 0.f;
        float s2 = (r2 < n) ? dinv[r2] : 0.f;
#pragma unroll
        for (int nt = 0; nt < 8; nt++) {
            int col = ncol0 + nt * 8 + ((lane & 3) << 1);
            if (r1 < n)
                *(__half2*)(Ch + (size_t)r1 * DD + col) =
                    __floats2half2_rn(acc[mt][nt][0] * s1, acc[mt][nt][1] * s1);
            if (r2 < n)
                *(__half2*)(Ch + (size_t)r2 * DD + col) =
                    __floats2half2_rn(acc[mt][nt][2] * s2, acc[mt][nt][3] * s2);
        }
    }
}

// ---------------------------------------------------------------------------
// Fused CSR gather + self-loop + bias + ELU. One warp per dst node.
// fp16 messages in, fp32 accumulate, fp32 out. Lane l owns 4 halves (uint2).
// ---------------------------------------------------------------------------
__device__ __forceinline__ float eluf(float x) { return x > 0.0f ? x : expm1f(x); }

__device__ __forceinline__ void acc_h4(float4& acc, uint2 u) {
    float2 f0 = __half22float2(*(const __half2*)&u.x);
    float2 f1 = __half22float2(*(const __half2*)&u.y);
    acc.x += f0.x; acc.y += f0.y; acc.z += f1.x; acc.w += f1.y;
}

__global__ __launch_bounds__(256) void k_gather(const __half* __restrict__ hp,
                                                const int* __restrict__ rowptr,
                                                const int* __restrict__ colv,
                                                const float* __restrict__ dinv,
                                                const float* __restrict__ b,
                                                float* __restrict__ outp, int n) {
    int d    = blockIdx.x * 8 + (threadIdx.x >> 5);
    int lane = threadIdx.x & 31;
    if (d >= n) return;

    const uint2* hp2 = (const uint2*)hp;   // 32 uint2 (= 4 halves each) per row

    int start = rowptr[d];
    int end   = rowptr[d + 1];

    float4 acc = make_float4(0.f, 0.f, 0.f, 0.f);
    acc_h4(acc, hp2[(size_t)d * 32 + lane]);   // self-loop

    for (int base = start; base < end; base += 32) {
        int cnt  = min(32, end - base);
        int sidx = (base + lane < end) ? colv[base + lane] : 0;
        int j = 0;
        for (; j + 4 <= cnt; j += 4) {
            int s0 = __shfl_sync(0xffffffffu, sidx, j);
            int s1 = __shfl_sync(0xffffffffu, sidx, j + 1);
            int s2 = __shfl_sync(0xffffffffu, sidx, j + 2);
            int s3 = __shfl_sync(0xffffffffu, sidx, j + 3);
            uint2 u0 = hp2[(size_t)s0 * 32 + lane];
            uint2 u1 = hp2[(size_t)s1 * 32 + lane];
            uint2 u2 = hp2[(size_t)s2 * 32 + lane];
            uint2 u3 = hp2[(size_t)s3 * 32 + lane];
            acc_h4(acc, u0);
            acc_h4(acc, u1);
            acc_h4(acc, u2);
            acc_h4(acc, u3);
        }
        for (; j < cnt; j++) {
            int s = __shfl_sync(0xffffffffu, sidx, j);
            acc_h4(acc, hp2[(size_t)s * 32 + lane]);
        }
    }

    float w = dinv[d];
    // lane owns cols [lane*4, lane*4+4)
    float4 bb = ((const float4*)b)[lane];
    acc.x = eluf(acc.x * w + bb.x);
    acc.y = eluf(acc.y * w + bb.y);
    acc.z = eluf(acc.z * w + bb.z);
    acc.w = eluf(acc.w * w + bb.w);
    ((float4*)outp)[(size_t)d * 32 + lane] = acc;
}

// ---------------------------------------------------------------------------
// Launch
// ---------------------------------------------------------------------------
extern "C" void kernel_launch(void* const* d_in, const int* in_sizes, int n_in,
                              void* d_out, int out_size) {
    const float* x  = (const float*)d_in[0];
    const int*   ei = (const int*)d_in[1];
    const float* W1 = (const float*)d_in[2];
    const float* b1 = (const float*)d_in[3];
    const float* W2 = (const float*)d_in[4];
    const float* b2 = (const float*)d_in[5];
    float* out = (float*)d_out;

    int N = in_sizes[0] / DD;
    int E = in_sizes[1] / 2;
    const int* src = ei;
    const int* dst = ei + E;

    float *dinv, *buf2;
    __half* hbuf;
    int *cnt, *rowptr, *cur, *col, *part;
    uint8_t* wb;
    cudaGetSymbolAddress((void**)&dinv, g_dinv);
    cudaGetSymbolAddress((void**)&hbuf, g_hbuf);
    cudaGetSymbolAddress((void**)&buf2, g_buf2);
    cudaGetSymbolAddress((void**)&cnt, g_cnt);
    cudaGetSymbolAddress((void**)&rowptr, g_rowptr);
    cudaGetSymbolAddress((void**)&cur, g_cur);
    cudaGetSymbolAddress((void**)&col, g_col);
    cudaGetSymbolAddress((void**)&part, g_part);
    cudaGetSymbolAddress((void**)&wb, g_wb);

    cudaFuncSetAttribute(k_gemm_mma, cudaFuncAttributeMaxDynamicSharedMemorySize,
                         GEMM_SMEM);

    const int T  = 256;
    int nb       = (N + 1023) / 1024;
    int egrid4   = (E / 4 + T - 1) / T;

    // CSR build + normalization
    cudaMemsetAsync(cnt, 0, (size_t)N * sizeof(int));
    k_hist<<<egrid4, T>>>(dst, cnt, E);
    k_scan_partial<<<nb, T>>>(cnt, part, N);
    k_scan_tops<<<1, 256>>>(part, rowptr + N, nb);
    k_scan_down<<<nb, T>>>(cnt, part, rowptr, cur, dinv, N);
    k_fill<<<egrid4, T>>>(src, dst, cur, col, E);

    int gemm_grid   = (N + 127) / 128;
    int gather_grid = (N + 7) / 8;

    // Layer 1
    k_wprep<<<64, 256>>>(W1, wb);
    k_gemm_mma<<<gemm_grid, 256, GEMM_SMEM>>>(x, wb, dinv, hbuf, N);
    k_gather<<<gather_grid, 256>>>(hbuf, rowptr, col, dinv, b1, buf2, N);

    // Layer 2
    k_wprep<<<64, 256>>>(W2, wb);
    k_gemm_mma<<<gemm_grid, 256, GEMM_SMEM>>>(buf2, wb, dinv, hbuf, N);
    k_gather<<<gather_grid, 256>>>(hbuf, rowptr, col, dinv, b2, out, N);
}